// round 14
// baseline (speedup 1.0000x reference)
#include <cuda_runtime.h>
#include <cuda_fp16.h>
#include <cstdint>

// ================= problem constants =================
#define Mdim 4096
#define Ndim 8192          // 4 gates x 2048, interleaved: n = col*4 + gate
#define Kdim 4096          // [x | h]
#define BM 128
#define BN 128
#define BK 64
#define NKT (Kdim / BK)    // 64
#define NTILES 2048        // (4096/128) * (8192/128)
#define THREADS 128        // 4 warps, 2m x 2n, warp tile 64x64; 2 CTAs/SM

// smem (halves): pitch 72 halves (144B) -> ldmatrix conflict-free
#define APITCH 72
#define BPITCH 72
#define AHALVES (BM * APITCH)            // 9216
#define BHALVES (BN * BPITCH)            // 9216
#define STAGE_H (AHALVES + BHALVES)      // 18432 halves = 36864 B
#define NSTAGE 3
#define BAR_OFF 512
#define STAGE_OFF 576
#define SMEM_BYTES (STAGE_OFF + NSTAGE * STAGE_H * 2)   // 111168 -> 2 CTAs/SM
// epilogue float buffers reuse stage region (pipeline fully drained per tile)
#define EPITCH 33
#define EBUF_W (BM * EPITCH)             // 4224 floats

// ================= scratch =================
__device__ __half g_A[(size_t)Mdim * Kdim];   // 32 MB, [m][k]
__device__ __half g_B[(size_t)Ndim * Kdim];   // 64 MB, [n][k] (transposed)

// ================= helpers =================
__device__ __forceinline__ uint32_t smem_u32(const void* p) {
    uint32_t a;
    asm("{ .reg .u64 t; cvta.to.shared.u64 t, %1; cvt.u32.u64 %0, t; }" : "=r"(a) : "l"(p));
    return a;
}
__device__ __forceinline__ void cp16(uint32_t dst, const void* src) {
    asm volatile("cp.async.cg.shared.global [%0], [%1], 16;" :: "r"(dst), "l"(src) : "memory");
}
#define MBAR_INIT(addr, cnt) \
    asm volatile("mbarrier.init.shared.b64 [%0], %1;" :: "r"(addr), "r"(cnt) : "memory")
__device__ __forceinline__ void mbar_arrive(uint32_t a) {
    asm volatile("mbarrier.arrive.release.cta.shared.b64 _, [%0];" :: "r"(a) : "memory");
}
__device__ __forceinline__ void cp_arrive_noinc(uint32_t a) {
    asm volatile("cp.async.mbarrier.arrive.noinc.shared.b64 [%0];" :: "r"(a) : "memory");
}
__device__ __forceinline__ void bar_wait(uint32_t mbar, uint32_t parity) {
    asm volatile(
        "{\n\t.reg .pred P;\n\t"
        "BW_%=:\n\t"
        "mbarrier.try_wait.parity.acquire.cta.shared::cta.b64 P, [%0], %1, 0x989680;\n\t"
        "@P bra.uni BD_%=;\n\t"
        "bra.uni BW_%=;\n\t"
        "BD_%=:\n\t}"
        :: "r"(mbar), "r"(parity) : "memory");
}

#define LDSM4(r0, r1, r2, r3, addr) \
    asm volatile("ldmatrix.sync.aligned.m8n8.x4.shared.b16 {%0,%1,%2,%3}, [%4];" \
        : "=r"(r0), "=r"(r1), "=r"(r2), "=r"(r3) : "r"(addr))

#define MMA16(acc, A, B) \
    asm volatile("mma.sync.aligned.m16n8k16.row.col.f32.f16.f16.f32 " \
        "{%0,%1,%2,%3}, {%4,%5,%6,%7}, {%8,%9}, {%0,%1,%2,%3};" \
        : "+f"((acc)[0]), "+f"((acc)[1]), "+f"((acc)[2]), "+f"((acc)[3]) \
        : "r"((A)[0]), "r"((A)[1]), "r"((A)[2]), "r"((A)[3]), \
          "r"((B)[0]), "r"((B)[1]))

__device__ __forceinline__ float sigm(float x) {
    return __fdividef(1.0f, 1.0f + __expf(-x));
}
__device__ __forceinline__ float tanh_f(float x) {
    float xc = fmaxf(fminf(x, 15.0f), -15.0f);
    float e = __expf(2.0f * xc);
    return __fdividef(e - 1.0f, e + 1.0f);
}

// ========== merged pre-pass: A convert + B transpose (one launch) ==========
// blocks [0,16384): A path.  blocks [16384,32768): B path (64kt x 64ct x 4g)
__global__ void __launch_bounds__(256) conv_kernel(
    const float* __restrict__ x,   const float* __restrict__ h,
    const float* __restrict__ wxi, const float* __restrict__ wxf,
    const float* __restrict__ wxo, const float* __restrict__ wxc,
    const float* __restrict__ whi, const float* __restrict__ whf,
    const float* __restrict__ who, const float* __restrict__ whc) {
    int tid = threadIdx.x;
    if (blockIdx.x < 16384) {
        size_t i = (size_t)blockIdx.x * 256 + tid;
        size_t row = i >> 10;
        size_t c4  = i & 1023;
        const float* src = (c4 < 512) ? (x + row * 2048 + c4 * 4)
                                      : (h + row * 2048 + (c4 - 512) * 4);
        float4 v = *(const float4*)src;
        *(__half2*)(g_A + row * 4096 + c4 * 4)     = __floats2half2_rn(v.x, v.y);
        *(__half2*)(g_A + row * 4096 + c4 * 4 + 2) = __floats2half2_rn(v.z, v.w);
    } else {
        __shared__ float tile[64][33];
        int bid = blockIdx.x - 16384;
        int kt = bid & 63;            // k-tile of 64
        int ct = (bid >> 6) & 63;     // col-tile of 32
        int g  = bid >> 12;           // gate
        int tx = tid & 31, ty = tid >> 5;
        int k0 = kt * 64, c0 = ct * 32;
        const float* src;
        int krel = k0 & 2047;
        if (k0 < 2048)
            src = (g == 0) ? wxi : (g == 1) ? wxf : (g == 2) ? wxo : wxc;
        else
            src = (g == 0) ? whi : (g == 1) ? whf : (g == 2) ? who : whc;
        #pragma unroll
        for (int r = ty; r < 64; r += 8)
            tile[r][tx] = src[(size_t)(krel + r) * 2048 + c0 + tx];
        __syncthreads();
        #pragma unroll
        for (int rr = ty; rr < 32; rr += 8) {
            size_t n = (size_t)(c0 + rr) * 4 + g;
            __half2 v = __floats2half2_rn(tile[2 * tx][rr], tile[2 * tx + 1][rr]);
            *(__half2*)(g_B + n * 4096 + k0 + 2 * tx) = v;   // 128B/row coalesced
        }
    }
}

// ================= persistent fused GEMM + LSTM (2 CTAs/SM) =================
__global__ void __launch_bounds__(THREADS, 2) lstm_gemm_kernel(
    const float* __restrict__ c_in,
    const float* __restrict__ b_i, const float* __restrict__ b_f,
    const float* __restrict__ b_o, const float* __restrict__ b_c,
    float* __restrict__ out) {
    extern __shared__ float sm[];
    float* bias_sm = sm;                       // 128 floats [hc*4+gate]
    const uint32_t sb = smem_u32(sm);
    const uint32_t bar_free  = sb + BAR_OFF;        // 3 x 8B (count 4: per-warp)
    const uint32_t bar_ready = sb + BAR_OFF + 24;   // 3 x 8B (cp noinc, count 128)
    const uint32_t stage_u32 = sb + STAGE_OFF;

    const int tid  = threadIdx.x;
    const int lane = tid & 31;
    const int wid  = tid >> 5;
    const int wm   = wid >> 1;                 // 0..1 -> m offset wm*64
    const int wn   = wid & 1;                  // 0..1 -> n offset wn*64

    if (tid == 0) {
        #pragma unroll
        for (int i = 0; i < 3; i++) MBAR_INIT(bar_free + i * 8, 4);
        #pragma unroll
        for (int i = 0; i < 3; i++) MBAR_INIT(bar_ready + i * 8, THREADS);
    }
    __syncthreads();
    if (lane == 0) {   // pre-arm all free barriers (each warp arrives once)
        mbar_arrive(bar_free + 0);
        mbar_arrive(bar_free + 8);
        mbar_arrive(bar_free + 16);
    }

    const uint32_t aoff = (uint32_t)((tid >> 3) * APITCH + (tid & 7) * 8) * 2;
    const uint32_t boff = (uint32_t)((tid >> 3) * BPITCH + (tid & 7) * 8) * 2;
    const int rsel = tid >> 3, csel = (tid & 7) * 8;

    const uint32_t a_lane_off =
        ((uint32_t)((wm * 64 + (lane & 15)) * APITCH + (lane >> 4) * 8)) * 2;
    const uint32_t b_lane_off =
        ((uint32_t)((wn * 64 + (lane & 7) + ((lane >> 4) << 3)) * BPITCH
                    + ((lane >> 3) & 1) * 8)) * 2;

    auto issueA = [&](int s, const __half* src) {
        uint32_t As = stage_u32 + (uint32_t)(s * STAGE_H) * 2;
        #pragma unroll
        for (int it = 0; it < 8; it++)
            cp16(As + aoff + (uint32_t)(it * 16 * APITCH) * 2,
                 src + (size_t)it * 16 * 4096);
    };
    auto issueB = [&](int s, const __half* src) {
        uint32_t Bs = stage_u32 + (uint32_t)(s * STAGE_H) * 2 + AHALVES * 2;
        #pragma unroll
        for (int it = 0; it < 8; it++)
            cp16(Bs + boff + (uint32_t)(it * 16 * BPITCH) * 2,
                 src + (size_t)it * 16 * 4096);
        cp_arrive_noinc(bar_ready + s * 8);
    };

    uint32_t af[2][16], bf[2][16];
    auto ldsm_chunk = [&](int buf, int s, int k16) {
        uint32_t As = stage_u32 + (uint32_t)(s * STAGE_H) * 2;
        uint32_t Bs = As + AHALVES * 2;
        uint32_t koff = (uint32_t)k16 * 32;
        #pragma unroll
        for (int ms = 0; ms < 4; ms++)
            LDSM4(af[buf][ms * 4 + 0], af[buf][ms * 4 + 1],
                  af[buf][ms * 4 + 2], af[buf][ms * 4 + 3],
                  As + a_lane_off + (uint32_t)(ms * 16 * APITCH) * 2 + koff);
        #pragma unroll
        for (int np = 0; np < 4; np++)
            LDSM4(bf[buf][np * 4 + 0], bf[buf][np * 4 + 1],
                  bf[buf][np * 4 + 2], bf[buf][np * 4 + 3],
                  Bs + b_lane_off + (uint32_t)(np * 16 * BPITCH) * 2 + koff);
    };

    float acc[4][8][4];
    auto mma_chunk = [&](int buf) {
        #pragma unroll
        for (int ms = 0; ms < 4; ms++)
            #pragma unroll
            for (int ns = 0; ns < 8; ns++)
                MMA16(acc[ms][ns], &af[buf][ms * 4],
                      &bf[buf][(ns >> 1) * 4 + (ns & 1) * 2]);
    };

    // running parity bitmask: bits 0..2 = free[s], bits 3..5 = ready[s]
    unsigned par = 0;
    auto waitp = [&](uint32_t addr, int bit) {
        bar_wait(addr, (par >> bit) & 1u);
        par ^= (1u << bit);
    };

    for (int T = blockIdx.x; T < NTILES; T += gridDim.x) {
        const int m0  = (T & 31) * BM;
        const int n0  = (T >> 5) * BN;
        const int hc0 = (T >> 5) * 32;

        const __half* pA = g_A + (size_t)(m0 + rsel) * 4096 + csel;
        const __half* pB = g_B + (size_t)(n0 + rsel) * 4096 + csel;

        {
            int g = tid & 3, hc = tid >> 2;
            const float* bp = (g == 0) ? b_i : (g == 1) ? b_f
                            : (g == 2) ? b_o : b_c;
            bias_sm[tid] = bp[hc0 + hc];
        }

        #pragma unroll
        for (int a = 0; a < 4; a++)
            #pragma unroll
            for (int b = 0; b < 8; b++)
                #pragma unroll
                for (int q = 0; q < 4; q++) acc[a][b][q] = 0.0f;

        // prologue: fill stages 0,1; preload chunk0 of stage0
        waitp(bar_free + 0, 0);
        issueA(0, pA);       issueB(0, pB);
        waitp(bar_free + 8, 1);
        issueA(1, pA + BK);  issueB(1, pB + BK);
        waitp(bar_ready + 0, 3);
        ldsm_chunk(0, 0, 0);

        auto iter = [&](int kt, int s, int s1, int s2) {
            bool more = (kt + 2 < NKT);
            if (more) {
                waitp(bar_free + s2 * 8, s2);
                issueA(s2, pA + (kt + 2) * BK);
            }
            // c0
            ldsm_chunk(1, s, 1);
            mma_chunk(0);
            if (more) issueB(s2, pB + (kt + 2) * BK);
            // c1
            ldsm_chunk(0, s, 2);
            mma_chunk(1);
            // c2: last smem read of stage s -> release
            ldsm_chunk(1, s, 3);
            if (lane == 0) mbar_arrive(bar_free + s * 8);
            mma_chunk(0);
            // c3: preload next stage chunk0, then final MMAs
            if (kt + 1 < NKT) {
                waitp(bar_ready + s1 * 8, 3 + s1);
                ldsm_chunk(0, s1, 0);
            }
            mma_chunk(1);
        };

        for (int g3 = 0; g3 < 21; g3++) {
            int kt = g3 * 3;
            iter(kt + 0, 0, 1, 2);
            iter(kt + 1, 1, 2, 0);
            iter(kt + 2, 2, 0, 1);
        }
        // tail kt=63 (s=0): chunk0 already preloaded
        ldsm_chunk(1, 0, 1);
        mma_chunk(0);
        ldsm_chunk(0, 0, 2);
        mma_chunk(1);
        ldsm_chunk(1, 0, 3);
        if (lane == 0) mbar_arrive(bar_free + 0);
        mma_chunk(0);
        mma_chunk(1);

        __syncthreads();

        // -------- epilogue (stage region reused; pipeline fully drained) ----
        float* ebase = sm + (STAGE_OFF / 4);
        float* cbuf  = ebase;
        float* hbuf  = ebase + EBUF_W;
        float* cobuf = ebase + 2 * EBUF_W;

        #pragma unroll
        for (int it = 0; it < 8; it++) {
            int idx = tid + it * THREADS;              // 1024 float4 loads
            int row = idx >> 3, q = idx & 7;
            float4 v = *(const float4*)(c_in + (size_t)(m0 + row) * 2048 + hc0 + q * 4);
            float* d = cbuf + row * EPITCH + q * 4;
            d[0] = v.x; d[1] = v.y; d[2] = v.z; d[3] = v.w;
        }
        __syncthreads();

        const bool odd = lane & 1;
        #pragma unroll
        for (int ms = 0; ms < 4; ms++) {
            #pragma unroll
            for (int ns = 0; ns < 8; ns++) {
                float t0 = __shfl_xor_sync(0xFFFFFFFFu, acc[ms][ns][0], 1);
                float t1 = __shfl_xor_sync(0xFFFFFFFFu, acc[ms][ns][1], 1);
                float t2 = __shfl_xor_sync(0xFFFFFFFFu, acc[ms][ns][2], 1);
                float t3 = __shfl_xor_sync(0xFFFFFFFFu, acc[ms][ns][3], 1);
                float gi = odd ? t2 : acc[ms][ns][0];
                float gf = odd ? t3 : acc[ms][ns][1];
                float go = odd ? acc[ms][ns][2] : t0;
                float gg = odd ? acc[ms][ns][3] : t1;
                int rowl = wm * 64 + ms * 16 + (lane >> 2) + (odd ? 8 : 0);
                int hc   = wn * 16 + ns * 2 + ((lane >> 1) & 1);
                gi += bias_sm[hc * 4 + 0];
                gf += bias_sm[hc * 4 + 1];
                go += bias_sm[hc * 4 + 2];
                gg += bias_sm[hc * 4 + 3];
                float it_ = sigm(gi);
                float ft_ = sigm(gf);
                float ot_ = sigm(go);
                float ct  = cbuf[rowl * EPITCH + hc] * ft_ + it_ * tanh_f(gg);
                float ht  = ot_ * tanh_f(ct);
                hbuf[rowl * EPITCH + hc]  = ht;
                cobuf[rowl * EPITCH + hc] = ct;
            }
        }
        __syncthreads();

        float* out_c = out + (size_t)4096 * 2048;
        #pragma unroll
        for (int it = 0; it < 8; it++) {
            int idx = tid + it * THREADS;
            int row = idx >> 3, q = idx & 7;
            size_t g = (size_t)(m0 + row) * 2048 + hc0 + q * 4;
            const float* hsrc = hbuf + row * EPITCH + q * 4;
            const float* csrc = cobuf + row * EPITCH + q * 4;
            float4 hv = {hsrc[0], hsrc[1], hsrc[2], hsrc[3]};
            float4 cv = {csrc[0], csrc[1], csrc[2], csrc[3]};
            *(float4*)(out + g)   = hv;
            *(float4*)(out_c + g) = cv;
        }
        __syncthreads();   // protect stage region before next tile's cps
    }
}

// ================= host =================
extern "C" void kernel_launch(void* const* d_in, const int* in_sizes, int n_in,
                              void* d_out, int out_size) {
    (void)in_sizes; (void)n_in; (void)out_size;
    const float* x    = (const float*)d_in[0];
    const float* h    = (const float*)d_in[1];
    const float* c    = (const float*)d_in[2];
    const float* w_xi = (const float*)d_in[3];
    const float* w_hi = (const float*)d_in[4];
    const float* w_xf = (const float*)d_in[5];
    const float* w_hf = (const float*)d_in[6];
    const float* w_xo = (const float*)d_in[7];
    const float* w_ho = (const float*)d_in[8];
    const float* w_xc = (const float*)d_in[9];
    const float* w_hc = (const float*)d_in[10];
    const float* b_i  = (const float*)d_in[11];
    const float* b_f  = (const float*)d_in[12];
    const float* b_o  = (const float*)d_in[13];
    const float* b_c  = (const float*)d_in[14];

    conv_kernel<<<32768, 256>>>(x, h, w_xi, w_xf, w_xo, w_xc,
                                w_hi, w_hf, w_ho, w_hc);

    int nsm = 148;
    cudaDeviceGetAttribute(&nsm, cudaDevAttrMultiProcessorCount, 0);
    if (nsm <= 0 || nsm > 1024) nsm = 148;

    cudaFuncSetAttribute(lstm_gemm_kernel,
                         cudaFuncAttributeMaxDynamicSharedMemorySize, SMEM_BYTES);
    lstm_gemm_kernel<<<2 * nsm, THREADS, SMEM_BYTES>>>(c, b_i, b_f, b_o, b_c,
                                                       (float*)d_out);
}

// round 15
// speedup vs baseline: 1.0684x; 1.0684x over previous
#include <cuda_runtime.h>
#include <cuda_fp16.h>
#include <cstdint>

// ================= problem constants =================
#define Mdim 4096
#define Ndim 8192          // 4 gates x 2048, interleaved: n = col*4 + gate
#define Kdim 4096          // [x | h]
#define BM 256
#define BN 128
#define BK 64
#define NKT (Kdim / BK)    // 64
#define NTILES 1024        // (4096/256) * (8192/128)
#define THREADS 256        // 8 warps, 4m x 2n, warp tile 64x64

// smem (halves): pitch 72 halves (144B) -> ldmatrix conflict-free
#define APITCH 72
#define BPITCH 72
#define AHALVES (BM * APITCH)            // 18432
#define BHALVES (BN * BPITCH)            // 9216
#define STAGE_H (AHALVES + BHALVES)      // 27648 halves = 55296 B
#define NSTAGE 4
#define BAR_OFF 512
#define STAGE_OFF 576
#define SMEM_BYTES (STAGE_OFF + NSTAGE * STAGE_H * 2)   // 221760
// epilogue float buffers live in stages 2..3 region (cross-tile cps hit 0..1 only)
#define EPITCH 33
#define EBUF_W (BM * EPITCH)             // 8448 floats; 3x = 101376 B <= 110592 B

// ================= scratch =================
__device__ __half g_A[(size_t)Mdim * Kdim];   // 32 MB, [m][k]
__device__ __half g_B[(size_t)Ndim * Kdim];   // 64 MB, [n][k] (transposed)

// ================= helpers =================
__device__ __forceinline__ uint32_t smem_u32(const void* p) {
    uint32_t a;
    asm("{ .reg .u64 t; cvta.to.shared.u64 t, %1; cvt.u32.u64 %0, t; }" : "=r"(a) : "l"(p));
    return a;
}
__device__ __forceinline__ void cp16(uint32_t dst, const void* src) {
    asm volatile("cp.async.cg.shared.global [%0], [%1], 16;" :: "r"(dst), "l"(src) : "memory");
}
#define MBAR_INIT(addr, cnt) \
    asm volatile("mbarrier.init.shared.b64 [%0], %1;" :: "r"(addr), "r"(cnt) : "memory")
__device__ __forceinline__ void mbar_arrive(uint32_t a) {
    asm volatile("mbarrier.arrive.release.cta.shared.b64 _, [%0];" :: "r"(a) : "memory");
}
__device__ __forceinline__ void cp_arrive_noinc(uint32_t a) {
    asm volatile("cp.async.mbarrier.arrive.noinc.shared.b64 [%0];" :: "r"(a) : "memory");
}
__device__ __forceinline__ void bar_wait(uint32_t mbar, uint32_t parity) {
    asm volatile(
        "{\n\t.reg .pred P;\n\t"
        "BW_%=:\n\t"
        "mbarrier.try_wait.parity.acquire.cta.shared::cta.b64 P, [%0], %1, 0x989680;\n\t"
        "@P bra.uni BD_%=;\n\t"
        "bra.uni BW_%=;\n\t"
        "BD_%=:\n\t}"
        :: "r"(mbar), "r"(parity) : "memory");
}

#define LDSM4(r0, r1, r2, r3, addr) \
    asm volatile("ldmatrix.sync.aligned.m8n8.x4.shared.b16 {%0,%1,%2,%3}, [%4];" \
        : "=r"(r0), "=r"(r1), "=r"(r2), "=r"(r3) : "r"(addr))

#define MMA16(acc, A, B) \
    asm volatile("mma.sync.aligned.m16n8k16.row.col.f32.f16.f16.f32 " \
        "{%0,%1,%2,%3}, {%4,%5,%6,%7}, {%8,%9}, {%0,%1,%2,%3};" \
        : "+f"((acc)[0]), "+f"((acc)[1]), "+f"((acc)[2]), "+f"((acc)[3]) \
        : "r"((A)[0]), "r"((A)[1]), "r"((A)[2]), "r"((A)[3]), \
          "r"((B)[0]), "r"((B)[1]))

__device__ __forceinline__ float sigm(float x) {
    return __fdividef(1.0f, 1.0f + __expf(-x));
}
__device__ __forceinline__ float tanh_f(float x) {
    float xc = fmaxf(fminf(x, 15.0f), -15.0f);
    float e = __expf(2.0f * xc);
    return __fdividef(e - 1.0f, e + 1.0f);
}

// ========== merged pre-pass: A convert + B transpose (one launch) ==========
// blocks [0,16384): A path.  blocks [16384,32768): B path (64kt x 64ct x 4g)
__global__ void __launch_bounds__(256) conv_kernel(
    const float* __restrict__ x,   const float* __restrict__ h,
    const float* __restrict__ wxi, const float* __restrict__ wxf,
    const float* __restrict__ wxo, const float* __restrict__ wxc,
    const float* __restrict__ whi, const float* __restrict__ whf,
    const float* __restrict__ who, const float* __restrict__ whc) {
    int tid = threadIdx.x;
    if (blockIdx.x < 16384) {
        size_t i = (size_t)blockIdx.x * 256 + tid;
        size_t row = i >> 10;
        size_t c4  = i & 1023;
        const float* src = (c4 < 512) ? (x + row * 2048 + c4 * 4)
                                      : (h + row * 2048 + (c4 - 512) * 4);
        float4 v = *(const float4*)src;
        *(__half2*)(g_A + row * 4096 + c4 * 4)     = __floats2half2_rn(v.x, v.y);
        *(__half2*)(g_A + row * 4096 + c4 * 4 + 2) = __floats2half2_rn(v.z, v.w);
    } else {
        __shared__ float tile[64][33];
        int bid = blockIdx.x - 16384;
        int kt = bid & 63;            // k-tile of 64
        int ct = (bid >> 6) & 63;     // col-tile of 32
        int g  = bid >> 12;           // gate
        int tx = tid & 31, ty = tid >> 5;
        int k0 = kt * 64, c0 = ct * 32;
        const float* src;
        int krel = k0 & 2047;
        if (k0 < 2048)
            src = (g == 0) ? wxi : (g == 1) ? wxf : (g == 2) ? wxo : wxc;
        else
            src = (g == 0) ? whi : (g == 1) ? whf : (g == 2) ? who : whc;
        #pragma unroll
        for (int r = ty; r < 64; r += 8)
            tile[r][tx] = src[(size_t)(krel + r) * 2048 + c0 + tx];
        __syncthreads();
        #pragma unroll
        for (int rr = ty; rr < 32; rr += 8) {
            size_t n = (size_t)(c0 + rr) * 4 + g;
            __half2 v = __floats2half2_rn(tile[2 * tx][rr], tile[2 * tx + 1][rr]);
            *(__half2*)(g_B + n * 4096 + k0 + 2 * tx) = v;   // 128B/row coalesced
        }
    }
}

// ================= persistent fused GEMM + LSTM =================
__global__ void __launch_bounds__(THREADS, 1) lstm_gemm_kernel(
    const float* __restrict__ c_in,
    const float* __restrict__ b_i, const float* __restrict__ b_f,
    const float* __restrict__ b_o, const float* __restrict__ b_c,
    float* __restrict__ out) {
    extern __shared__ float sm[];
    float* bias_sm = sm;                       // 128 floats [hc*4+gate]
    const uint32_t sb = smem_u32(sm);
    const uint32_t bar_free  = sb + BAR_OFF;        // 4 x 8B (count 8: per-warp)
    const uint32_t bar_ready = sb + BAR_OFF + 32;   // 4 x 8B (cp noinc)
    const uint32_t stage_u32 = sb + STAGE_OFF;

    const int tid  = threadIdx.x;
    const int lane = tid & 31;
    const int wid  = tid >> 5;
    const int wm   = wid >> 1;
    const int wn   = wid & 1;

    if (tid == 0) {
        #pragma unroll
        for (int i = 0; i < 4; i++) MBAR_INIT(bar_free + i * 8, 8);
        #pragma unroll
        for (int i = 0; i < 4; i++) MBAR_INIT(bar_ready + i * 8, THREADS);
    }
    __syncthreads();
    // pre-arm free[2], free[3] once (stages written at global kt=0,1)
    if (lane == 0) {
        mbar_arrive(bar_free + 2 * 8);
        mbar_arrive(bar_free + 3 * 8);
    }

    // per-thread cp dst offsets (fixed)
    const uint32_t aoff = (uint32_t)((tid >> 3) * APITCH + (tid & 7) * 8) * 2;
    const uint32_t boff = (uint32_t)((tid >> 3) * BPITCH + (tid & 7) * 8) * 2;
    const int rsel = tid >> 3, csel = (tid & 7) * 8;

    const uint32_t a_lane_off =
        ((uint32_t)((wm * 64 + (lane & 15)) * APITCH + (lane >> 4) * 8)) * 2;
    const uint32_t b_lane_off =
        ((uint32_t)((wn * 64 + (lane & 7) + ((lane >> 4) << 3)) * BPITCH
                    + ((lane >> 3) & 1) * 8)) * 2;

    auto issueA = [&](int s, const __half* src) {
        uint32_t As = stage_u32 + (uint32_t)(s * STAGE_H) * 2;
        #pragma unroll
        for (int it = 0; it < 8; it++)
            cp16(As + aoff + (uint32_t)(it * 32 * APITCH) * 2,
                 src + (size_t)it * 32 * 4096);
    };
    auto issueB = [&](int s, const __half* src) {
        uint32_t Bs = stage_u32 + (uint32_t)(s * STAGE_H) * 2 + AHALVES * 2;
        #pragma unroll
        for (int it = 0; it < 4; it++)
            cp16(Bs + boff + (uint32_t)(it * 32 * BPITCH) * 2,
                 src + (size_t)it * 32 * 4096);
        cp_arrive_noinc(bar_ready + s * 8);
    };

    uint32_t af[2][16], bf[2][16];
    auto ldsm_chunk = [&](int buf, uint32_t As, uint32_t Bs, int k16) {
        uint32_t koff = (uint32_t)k16 * 32;
        #pragma unroll
        for (int ms = 0; ms < 4; ms++)
            LDSM4(af[buf][ms * 4 + 0], af[buf][ms * 4 + 1],
                  af[buf][ms * 4 + 2], af[buf][ms * 4 + 3],
                  As + a_lane_off + (uint32_t)(ms * 16 * APITCH) * 2 + koff);
        #pragma unroll
        for (int np = 0; np < 4; np++)
            LDSM4(bf[buf][np * 4 + 0], bf[buf][np * 4 + 1],
                  bf[buf][np * 4 + 2], bf[buf][np * 4 + 3],
                  Bs + b_lane_off + (uint32_t)(np * 16 * BPITCH) * 2 + koff);
    };

    float acc[4][8][4];
    auto mma_chunk = [&](int buf) {
        #pragma unroll
        for (int ms = 0; ms < 4; ms++)
            #pragma unroll
            for (int ns = 0; ns < 8; ns++)
                MMA16(acc[ms][ns], &af[buf][ms * 4],
                      &bf[buf][(ns >> 1) * 4 + (ns & 1) * 2]);
    };

    const int firstT = blockIdx.x;

    for (int T = firstT; T < NTILES; T += gridDim.x) {
        const int m0  = (T & 15) * BM;
        const int n0  = (T >> 4) * BN;
        const int hc0 = (T >> 4) * 32;
        const int T2  = T + gridDim.x;
        const bool hasNext = (T2 < NTILES);
        const int m0n = hasNext ? (T2 & 15) * BM : 0;
        const int n0n = hasNext ? (T2 >> 4) * BN : 0;

        const __half* pA = g_A + (size_t)(m0 + rsel) * 4096 + csel;
        const __half* pB = g_B + (size_t)(n0 + rsel) * 4096 + csel;
        const __half* pAn = g_A + (size_t)(m0n + rsel) * 4096 + csel;
        const __half* pBn = g_B + (size_t)(n0n + rsel) * 4096 + csel;

        if (tid < 128) {
            int g = tid & 3, hc = tid >> 2;
            const float* bp = (g == 0) ? b_i : (g == 1) ? b_f
                            : (g == 2) ? b_o : b_c;
            bias_sm[tid] = bp[hc0 + hc];
        }

        #pragma unroll
        for (int a = 0; a < 4; a++)
            #pragma unroll
            for (int b = 0; b < 8; b++)
                #pragma unroll
                for (int q = 0; q < 4; q++) acc[a][b][q] = 0.0f;

        if (T == firstT) {                     // only very first tile self-feeds
            issueA(0, pA);       issueB(0, pB);
            issueA(1, pA + BK);  issueB(1, pB + BK);
        }

        // prologue: stage0 data ready (armed 16x/tile -> parity always 0)
        bar_wait(bar_ready + 0, 0);
        ldsm_chunk(0, stage_u32, stage_u32 + AHALVES * 2, 0);

        auto iter = [&](int kt, int s, int P) {
            uint32_t As = stage_u32 + (uint32_t)(s * STAGE_H) * 2;
            uint32_t Bs = As + AHALVES * 2;
            int s1 = (s + 1) & 3, s2 = (s + 2) & 3;
            bar_wait(bar_free + s2 * 8, (uint32_t)P);
            int ktt = kt + 2;
            bool doIssue = (ktt < NKT) || hasNext;
            const __half* sA;
            const __half* sB;
            if (ktt < NKT) { sA = pA + ktt * BK;          sB = pB + ktt * BK; }
            else           { sA = pAn + (ktt - NKT) * BK; sB = pBn + (ktt - NKT) * BK; }
            if (doIssue) issueA(s2, sA);
            // c0
            ldsm_chunk(1, As, Bs, 1);
            mma_chunk(0);
            if (doIssue) issueB(s2, sB);
            // c1
            ldsm_chunk(0, As, Bs, 2);
            mma_chunk(1);
            // c2: last smem read of stage s -> release it
            ldsm_chunk(1, As, Bs, 3);
            if (lane == 0) mbar_arrive(bar_free + s * 8);
            mma_chunk(0);
            // c3: ready-wait + next-stage chunk0 prefetch BEFORE final MMAs
            if (kt + 1 < NKT) {
                uint32_t Pr = (uint32_t)((s == 3) ? (P ^ 1) : P);
                bar_wait(bar_ready + s1 * 8, Pr);
                uint32_t As2 = stage_u32 + (uint32_t)(s1 * STAGE_H) * 2;
                ldsm_chunk(0, As2, As2 + AHALVES * 2, 0);
            }
            mma_chunk(1);
        };

        int P = 0;
        for (int kt4 = 0; kt4 < NKT; kt4 += 4) {
            iter(kt4 + 0, 0, P);
            iter(kt4 + 1, 1, P);
            iter(kt4 + 2, 2, P);
            iter(kt4 + 3, 3, P);
            P ^= 1;
        }

        __syncthreads();

        // -------- epilogue (buffers in stages 2..3 region) --------
        float* ebase = sm + (STAGE_OFF / 4) + STAGE_H;   // 2 stages * STAGE_H/2 floats
        float* cbuf  = ebase;
        float* hbuf  = ebase + EBUF_W;
        float* cobuf = ebase + 2 * EBUF_W;

        #pragma unroll
        for (int it = 0; it < 8; it++) {
            int idx = tid + it * THREADS;
            int row = idx >> 3, q = idx & 7;
            float4 v = *(const float4*)(c_in + (size_t)(m0 + row) * 2048 + hc0 + q * 4);
            float* d = cbuf + row * EPITCH + q * 4;
            d[0] = v.x; d[1] = v.y; d[2] = v.z; d[3] = v.w;
        }
        __syncthreads();

        const bool odd = lane & 1;
        #pragma unroll
        for (int ms = 0; ms < 4; ms++) {
            #pragma unroll
            for (int ns = 0; ns < 8; ns++) {
                float t0 = __shfl_xor_sync(0xFFFFFFFFu, acc[ms][ns][0], 1);
                float t1 = __shfl_xor_sync(0xFFFFFFFFu, acc[ms][ns][1], 1);
                float t2 = __shfl_xor_sync(0xFFFFFFFFu, acc[ms][ns][2], 1);
                float t3 = __shfl_xor_sync(0xFFFFFFFFu, acc[ms][ns][3], 1);
                float gi = odd ? t2 : acc[ms][ns][0];
                float gf = odd ? t3 : acc[ms][ns][1];
                float go = odd ? acc[ms][ns][2] : t0;
                float gg = odd ? acc[ms][ns][3] : t1;
                int rowl = wm * 64 + ms * 16 + (lane >> 2) + (odd ? 8 : 0);
                int hc   = wn * 16 + ns * 2 + ((lane >> 1) & 1);
                gi += bias_sm[hc * 4 + 0];
                gf += bias_sm[hc * 4 + 1];
                go += bias_sm[hc * 4 + 2];
                gg += bias_sm[hc * 4 + 3];
                float it_ = sigm(gi);
                float ft_ = sigm(gf);
                float ot_ = sigm(go);
                float ct  = cbuf[rowl * EPITCH + hc] * ft_ + it_ * tanh_f(gg);
                float ht  = ot_ * tanh_f(ct);
                hbuf[rowl * EPITCH + hc]  = ht;
                cobuf[rowl * EPITCH + hc] = ct;
            }
        }
        __syncthreads();

        float* out_c = out + (size_t)4096 * 2048;
        #pragma unroll
        for (int it = 0; it < 8; it++) {
            int idx = tid + it * THREADS;
            int row = idx >> 3, q = idx & 7;
            size_t g = (size_t)(m0 + row) * 2048 + hc0 + q * 4;
            const float* hsrc = hbuf + row * EPITCH + q * 4;
            const float* csrc = cobuf + row * EPITCH + q * 4;
            float4 hv = {hsrc[0], hsrc[1], hsrc[2], hsrc[3]};
            float4 cv = {csrc[0], csrc[1], csrc[2], csrc[3]};
            *(float4*)(out + g)   = hv;
            *(float4*)(out_c + g) = cv;
        }
        __syncthreads();   // protect stage-2/3 region before next tile's cps
    }
}

// ================= host =================
extern "C" void kernel_launch(void* const* d_in, const int* in_sizes, int n_in,
                              void* d_out, int out_size) {
    (void)in_sizes; (void)n_in; (void)out_size;
    const float* x    = (const float*)d_in[0];
    const float* h    = (const float*)d_in[1];
    const float* c    = (const float*)d_in[2];
    const float* w_xi = (const float*)d_in[3];
    const float* w_hi = (const float*)d_in[4];
    const float* w_xf = (const float*)d_in[5];
    const float* w_hf = (const float*)d_in[6];
    const float* w_xo = (const float*)d_in[7];
    const float* w_ho = (const float*)d_in[8];
    const float* w_xc = (const float*)d_in[9];
    const float* w_hc = (const float*)d_in[10];
    const float* b_i  = (const float*)d_in[11];
    const float* b_f  = (const float*)d_in[12];
    const float* b_o  = (const float*)d_in[13];
    const float* b_c  = (const float*)d_in[14];

    conv_kernel<<<32768, 256>>>(x, h, w_xi, w_xf, w_xo, w_xc,
                                w_hi, w_hf, w_ho, w_hc);

    int nsm = 148;
    cudaDeviceGetAttribute(&nsm, cudaDevAttrMultiProcessorCount, 0);
    if (nsm <= 0 || nsm > 1024) nsm = 148;

    cudaFuncSetAttribute(lstm_gemm_kernel,
                         cudaFuncAttributeMaxDynamicSharedMemorySize, SMEM_BYTES);
    lstm_gemm_kernel<<<nsm, THREADS, SMEM_BYTES>>>(c, b_i, b_f, b_o, b_c, (float*)d_out);
}